// round 3
// baseline (speedup 1.0000x reference)
#include <cuda_runtime.h>
#include <math.h>

#define NN 4096
#define NB 128           /* blocks: must all be co-resident (<=148 SMs) */
#define NT 256           /* threads per block */
#define CEXP 144.269504089f   /* (1/TAU) * log2(e) */
#define RWIN 0.3725f          /* sqrt(20 / CEXP): exp2 term < 2^-20 beyond */

static __device__ float g_xs[NN + 4];   // preds sorted ascending (+padding)
static __device__ float g_ts[NN + 4];   // target permuted alongside (+padding)
static __device__ float g_y[NN];        // y_sorted
static __device__ float g_ss[NN];       // s = 100*y sorted DESCENDING
static __device__ int   g_sidx[NN];     // original indices of that sort

static __device__ unsigned g_bar_cnt = 0;
static __device__ unsigned g_bar_gen = 0;

// Software grid barrier (all NB blocks resident; generation persists across
// graph replays — equality test on the generation makes it replay-safe).
__device__ __forceinline__ void grid_barrier() {
    __syncthreads();
    if (threadIdx.x == 0) {
        __threadfence();
        unsigned gen = *((volatile unsigned*)&g_bar_gen);
        unsigned t = atomicAdd(&g_bar_cnt, 1u);
        if (t == NB - 1u) {
            atomicExch(&g_bar_cnt, 0u);
            __threadfence();
            atomicAdd(&g_bar_gen, 1u);
        } else {
            while (*((volatile unsigned*)&g_bar_gen) == gen) {}
            __threadfence();
        }
    }
    __syncthreads();
}

__global__ void __launch_bounds__(NT, 1)
xi_fused_kernel(const float* __restrict__ preds,
                const float* __restrict__ target,
                float* out, int out_size) {
    extern __shared__ char smem_raw[];
    const unsigned FULL = 0xffffffffu;
    const int tid  = threadIdx.x;
    const int lane = tid & 31;
    const int warp = tid >> 5;
    const int gw   = blockIdx.x * (NT / 32) + warp;   // global warp id [0,1024)

    // ---------------- Phase A: rank-by-count sort of (preds, target) --------
    {
        float* sx = (float*)smem_raw;
        for (int i = tid; i < NN; i += NT) sx[i] = preds[i];
        __syncthreads();
        int row = gw * 4 + (lane >> 3);   // 4 rows per warp, 8 lanes per row
        int q   = lane & 7;
        float xi = sx[row];
        int cnt = 0;
        #pragma unroll 4
        for (int t = 0; t < NN / 32; t++) {
            int j = t * 32 + q * 4;
            float4 v = *reinterpret_cast<const float4*>(sx + j);
            cnt += (v.x < xi) || (v.x == xi && (j + 0) < row);
            cnt += (v.y < xi) || (v.y == xi && (j + 1) < row);
            cnt += (v.z < xi) || (v.z == xi && (j + 2) < row);
            cnt += (v.w < xi) || (v.w == xi && (j + 3) < row);
        }
        cnt += __shfl_xor_sync(FULL, cnt, 1);
        cnt += __shfl_xor_sync(FULL, cnt, 2);
        cnt += __shfl_xor_sync(FULL, cnt, 4);
        if (q == 0) { g_xs[cnt] = xi; g_ts[cnt] = target[row]; }
        if (blockIdx.x == 0 && tid < 4) {
            g_xs[NN + tid] = 1e30f; g_ts[NN + tid] = 0.0f;
        }
    }
    grid_barrier();

    // ---------------- Phase B: windowed soft-perm  y = P @ t ----------------
    {
        float* sx = (float*)smem_raw;             // NN+4
        float* st = sx + (NN + 4);                // NN+4
        for (int i = tid; i < NN + 4; i += NT) { sx[i] = g_xs[i]; st[i] = g_ts[i]; }
        __syncthreads();

        for (int rr = 0; rr < 4; rr++) {
            int row = gw * 4 + rr;
            float xv = sx[row];

            int lim = 0;
            if (lane < 2) {
                float tgt = (lane == 0) ? (xv - RWIN) : (xv + RWIN);
                int l = 0, r = NN;
                while (l < r) {
                    int m = (l + r) >> 1;
                    bool go = (lane == 0) ? (sx[m] < tgt) : (sx[m] <= tgt);
                    if (go) l = m + 1; else r = m;
                }
                lim = l;
            }
            int lo = __shfl_sync(FULL, lim, 0);
            int hi = __shfl_sync(FULL, lim, 1);

            float se = 0.f, sum = 0.f;
            int j0 = (lo & ~3) + lane * 4;
            for (int j = j0; j < hi; j += 128) {
                float4 x4 = *reinterpret_cast<const float4*>(sx + j);
                float4 t4 = *reinterpret_cast<const float4*>(st + j);
                float d0 = xv - x4.x, d1 = xv - x4.y, d2 = xv - x4.z, d3 = xv - x4.w;
                float a0 = (d0 * d0) * (-CEXP);
                float a1 = (d1 * d1) * (-CEXP);
                float a2 = (d2 * d2) * (-CEXP);
                float a3 = (d3 * d3) * (-CEXP);
                float e0, e1, e2, e3;
                asm("ex2.approx.f32 %0, %1;" : "=f"(e0) : "f"(a0));
                asm("ex2.approx.f32 %0, %1;" : "=f"(e1) : "f"(a1));
                asm("ex2.approx.f32 %0, %1;" : "=f"(e2) : "f"(a2));
                asm("ex2.approx.f32 %0, %1;" : "=f"(e3) : "f"(a3));
                se += e0 + e1 + e2 + e3;
                sum = fmaf(e0, t4.x, sum);
                sum = fmaf(e1, t4.y, sum);
                sum = fmaf(e2, t4.z, sum);
                sum = fmaf(e3, t4.w, sum);
            }
            for (int off = 16; off; off >>= 1) {
                se  += __shfl_down_sync(FULL, se, off);
                sum += __shfl_down_sync(FULL, sum, off);
            }
            if (lane == 0) g_y[row] = sum / se;
        }
    }
    grid_barrier();

    // ---------------- Phase D: descending argsort of y by counting ----------
    {
        float* sy = (float*)smem_raw;
        for (int i = tid; i < NN; i += NT) sy[i] = g_y[i];
        __syncthreads();
        int row = gw * 4 + (lane >> 3);
        int q   = lane & 7;
        float yi = sy[row];
        int cnt = 0;
        #pragma unroll 4
        for (int t = 0; t < NN / 32; t++) {
            int j = t * 32 + q * 4;
            float4 v = *reinterpret_cast<const float4*>(sy + j);
            cnt += (v.x > yi) || (v.x == yi && (j + 0) < row);
            cnt += (v.y > yi) || (v.y == yi && (j + 1) < row);
            cnt += (v.z > yi) || (v.z == yi && (j + 2) < row);
            cnt += (v.w > yi) || (v.w == yi && (j + 3) < row);
        }
        cnt += __shfl_xor_sync(FULL, cnt, 1);
        cnt += __shfl_xor_sync(FULL, cnt, 2);
        cnt += __shfl_xor_sync(FULL, cnt, 4);
        if (q == 0) { g_ss[cnt] = yi * 100.0f; g_sidx[cnt] = row; }
    }
    grid_barrier();

    // ---------------- Phase C: PAV soft-rank + loss (block 0 only) ----------
    if (blockIdx.x != 0) return;
    {
        float* s      = (float*)smem_raw;             // NN (descending)
        int*   idx    = (int*)(s + NN);               // NN
        float* bsum   = (float*)(idx + NN);           // NN
        int*   bcnt   = (int*)(bsum + NN);            // NN
        int*   bstart = (int*)(bcnt + NN);            // NN+1
        int*   fstart = (int*)(bstart + NN + 1);      // NN+1
        float* fmean  = (float*)(fstart + NN + 1);    // NN
        float* r      = (float*)(fmean + NN);         // NN (zc, then ranks)

        __shared__ int   warpTotI[8];
        __shared__ float warpTotF[8];
        __shared__ int   warpOffI[8];
        __shared__ float warpOffF[8];
        __shared__ int   s_m, s_nb;
        __shared__ float s_red[8];

        __syncthreads();   // smem reuse fence
        for (int i = tid; i < NN; i += NT) { s[i] = g_ss[i]; idx[i] = g_sidx[i]; }
        __syncthreads();

        const int E = NN / NT;            // 16 elements per thread
        const int base = tid * E;

        // pass 1: per-thread totals of boundary flags and z values
        int cb = 0; float zt = 0.f;
        {
            float prev = (tid == 0) ? s[0] : s[base - 1];
            #pragma unroll
            for (int e = 0; e < E; e++) {
                float cur = s[base + e];
                cb += (prev - cur > 1.0f);
                zt += cur - (float)(NN - (base + e));
                prev = cur;
            }
        }
        // warp inclusive scans
        int ic = cb; float fc = zt;
        for (int off = 1; off < 32; off <<= 1) {
            int   ui = __shfl_up_sync(FULL, ic, off);
            float uf = __shfl_up_sync(FULL, fc, off);
            if (lane >= off) { ic += ui; fc += uf; }
        }
        if (lane == 31) { warpTotI[warp] = ic; warpTotF[warp] = fc; }
        __syncthreads();
        if (warp == 0 && lane < 8) {
            int   ti = warpTotI[lane];
            float tf = warpTotF[lane];
            int   vi = ti; float vf = tf;
            for (int off = 1; off < 8; off <<= 1) {
                int   ui = __shfl_up_sync(0xffu, vi, off);
                float uf = __shfl_up_sync(0xffu, vf, off);
                if (lane >= off) { vi += ui; vf += uf; }
            }
            warpOffI[lane] = vi - ti;
            warpOffF[lane] = vf - tf;
        }
        __syncthreads();
        int   exI = warpOffI[warp] + (ic - cb);
        float exF = warpOffF[warp] + (fc - zt);

        // pass 2: write bstart and zc prefix (into r)
        {
            float prev = (tid == 0) ? s[0] : s[base - 1];
            int cc = exI; float zc = exF;
            #pragma unroll
            for (int e = 0; e < E; e++) {
                int k = base + e;
                float cur = s[k];
                int b = (prev - cur > 1.0f);
                cc += b;
                if (b) bstart[cc] = k;
                zc += cur - (float)(NN - k);
                r[k] = zc;
                prev = cur;
            }
            if (tid == 0) bstart[0] = 0;
            if (tid == NT - 1) { s_m = cc + 1; bstart[cc + 1] = NN; }
        }
        __syncthreads();

        // pre-block sums/counts
        int m = s_m;
        for (int b = tid; b < m; b += NT) {
            int st_ = bstart[b], en = bstart[b + 1];
            float lo_ = (st_ > 0) ? r[st_ - 1] : 0.f;
            bsum[b] = r[en - 1] - lo_;
            bcnt[b] = en - st_;
        }
        __syncthreads();

        // serial PAV over m pre-blocks (thread 0)
        if (tid == 0) {
            int sp = 0;
            float tsum = bsum[0];
            float tcnt = (float)bcnt[0];
            int   tst  = 0;
            for (int b = 1; b < m; b++) {
                float nsum = bsum[b];
                float ncnt = (float)bcnt[b];
                int   nst  = bstart[b];
                bool havetop = true;
                while (havetop && tsum * ncnt <= nsum * tcnt) {
                    nsum += tsum; ncnt += tcnt; nst = tst;
                    if (sp > 0) {
                        sp--;
                        tsum = bsum[sp]; tcnt = (float)bcnt[sp]; tst = bstart[sp];
                    } else {
                        havetop = false;
                    }
                }
                if (havetop) {
                    bsum[sp] = tsum; bcnt[sp] = (int)tcnt; bstart[sp] = tst; sp++;
                }
                tsum = nsum; tcnt = ncnt; tst = nst;
            }
            for (int q_ = 0; q_ < sp; q_++) {
                fstart[q_] = bstart[q_];
                fmean[q_]  = bsum[q_] / (float)bcnt[q_];
            }
            fstart[sp] = tst;
            fmean[sp]  = tsum / tcnt;
            fstart[sp + 1] = NN;
            s_nb = sp + 1;
        }
        __syncthreads();

        // expand + scatter r[idx[k]] = s[k] - v(block(k))
        int nb = s_nb;
        for (int k = tid; k < NN; k += NT) {
            int l = 0, h = nb;
            while (l + 1 < h) {
                int mid = (l + h) >> 1;
                if (fstart[mid] <= k) l = mid; else h = mid;
            }
            float val = s[k] - fmean[l];
            r[idx[k]] = val;
        }
        __syncthreads();

        float acc = 0.f;
        for (int i = tid; i < NN - 1; i += NT) acc += fabsf(r[i + 1] - r[i]);
        for (int off = 16; off; off >>= 1) acc += __shfl_down_sync(FULL, acc, off);
        if (lane == 0) s_red[warp] = acc;
        __syncthreads();
        if (warp == 0 && lane < 8) {
            float a2 = s_red[lane];
            for (int off = 4; off; off >>= 1) a2 += __shfl_down_sync(0xffu, a2, off);
            if (lane == 0) {
                float xi = 1.0f - 3.0f * a2 / ((float)NN * (float)NN - 1.0f);
                out[0] = -xi;
                if (out_size > 1) out[1] = xi;
            }
        }
    }
}

// ---------------------------------------------------------------------------
extern "C" void kernel_launch(void* const* d_in, const int* in_sizes, int n_in,
                              void* d_out, int out_size) {
    const float* preds  = (const float*)d_in[0];
    const float* target = (const float*)d_in[1];
    float* out = (float*)d_out;

    size_t smem = (size_t)(8 * NN + 2) * sizeof(float) + 32;
    static int configured = 0;
    if (!configured) {   // host-side attribute set; not device work
        cudaFuncSetAttribute(xi_fused_kernel,
                             cudaFuncAttributeMaxDynamicSharedMemorySize,
                             (int)smem);
        configured = 1;
    }
    xi_fused_kernel<<<NB, NT, smem>>>(preds, target, out, out_size);
}

// round 4
// speedup vs baseline: 1.9022x; 1.9022x over previous
#include <cuda_runtime.h>
#include <math.h>

#define NN 4096
#define CEXP 144.269504089f   /* (1/TAU) * log2(e) */
#define RWIN 0.3725f          /* sqrt(20 / CEXP): exp2 term < 2^-20 beyond */

static __device__ float g_xs[NN + 4];   // preds sorted ascending (+padding)
static __device__ float g_ts[NN + 4];   // target permuted alongside (+padding)
static __device__ float g_y[NN];        // y_sorted
static __device__ float g_ss[NN];       // s = 100*y sorted DESCENDING
static __device__ int   g_sidx[NN];     // original indices of that sort

// ---------------------------------------------------------------------------
// Kernel A: rank-by-count sort of (preds, target) by preds ascending.
// 256 blocks x 256 thr. 2 rows per warp, 16 lanes per row, float4 broadcast.
// ---------------------------------------------------------------------------
__global__ void __launch_bounds__(256)
rank_scatter_pairs(const float* __restrict__ preds,
                   const float* __restrict__ target) {
    const unsigned FULL = 0xffffffffu;
    __shared__ float sx[NN];
    float4* sx4 = (float4*)sx;
    const float4* p4 = (const float4*)preds;
    for (int i = threadIdx.x; i < NN / 4; i += 256) sx4[i] = p4[i];
    __syncthreads();

    int gw   = blockIdx.x * 8 + (threadIdx.x >> 5);
    int lane = threadIdx.x & 31;
    int row  = gw * 2 + (lane >> 4);
    int q    = lane & 15;
    float xi = sx[row];
    int cnt = 0;
    #pragma unroll 8
    for (int t = 0; t < NN / 64; t++) {
        int j = t * 64 + q * 4;
        float4 v = sx4[j >> 2];
        cnt += (v.x < xi) || (v.x == xi && (j + 0) < row);
        cnt += (v.y < xi) || (v.y == xi && (j + 1) < row);
        cnt += (v.z < xi) || (v.z == xi && (j + 2) < row);
        cnt += (v.w < xi) || (v.w == xi && (j + 3) < row);
    }
    cnt += __shfl_xor_sync(FULL, cnt, 1);
    cnt += __shfl_xor_sync(FULL, cnt, 2);
    cnt += __shfl_xor_sync(FULL, cnt, 4);
    cnt += __shfl_xor_sync(FULL, cnt, 8);
    if (q == 0) {
        g_xs[cnt] = xi;
        g_ts[cnt] = target[row];
    }
    if (blockIdx.x == 0 && threadIdx.x < 4) {
        g_xs[NN + threadIdx.x] = 1e30f;
        g_ts[NN + threadIdx.x] = 0.0f;
    }
}

// ---------------------------------------------------------------------------
// Kernel B: y_sorted[i] = softmax_j(-(xs_i - x_j)^2/tau) . t_j
// One warp per row; window via binary search; terms outside < 2^-20.
// ---------------------------------------------------------------------------
__global__ void __launch_bounds__(256)
ysoft_kernel() {
    const unsigned FULL = 0xffffffffu;
    const int lane = threadIdx.x & 31;
    const int warp = threadIdx.x >> 5;
    const int row = blockIdx.x * 8 + warp;
    const float xv = g_xs[row];

    int lim = 0;
    if (lane < 2) {
        float tgt = (lane == 0) ? (xv - RWIN) : (xv + RWIN);
        int l = 0, r = NN;
        while (l < r) {
            int m = (l + r) >> 1;
            bool go = (lane == 0) ? (g_xs[m] < tgt) : (g_xs[m] <= tgt);
            if (go) l = m + 1; else r = m;
        }
        lim = l;
    }
    int lo = __shfl_sync(FULL, lim, 0);
    int hi = __shfl_sync(FULL, lim, 1);

    float se = 0.f, st = 0.f;
    int j0 = (lo & ~3) + lane * 4;
    for (int j = j0; j < hi; j += 128) {
        float4 x4 = *reinterpret_cast<const float4*>(g_xs + j);
        float4 t4 = *reinterpret_cast<const float4*>(g_ts + j);
        float d0 = xv - x4.x, d1 = xv - x4.y, d2 = xv - x4.z, d3 = xv - x4.w;
        float a0 = (d0 * d0) * (-CEXP);
        float a1 = (d1 * d1) * (-CEXP);
        float a2 = (d2 * d2) * (-CEXP);
        float a3 = (d3 * d3) * (-CEXP);
        float e0, e1, e2, e3;
        asm("ex2.approx.f32 %0, %1;" : "=f"(e0) : "f"(a0));
        asm("ex2.approx.f32 %0, %1;" : "=f"(e1) : "f"(a1));
        asm("ex2.approx.f32 %0, %1;" : "=f"(e2) : "f"(a2));
        asm("ex2.approx.f32 %0, %1;" : "=f"(e3) : "f"(a3));
        se += e0 + e1 + e2 + e3;
        st = fmaf(e0, t4.x, st);
        st = fmaf(e1, t4.y, st);
        st = fmaf(e2, t4.z, st);
        st = fmaf(e3, t4.w, st);
    }
    for (int off = 16; off; off >>= 1) {
        se += __shfl_down_sync(FULL, se, off);
        st += __shfl_down_sync(FULL, st, off);
    }
    if (lane == 0) g_y[row] = st / se;
}

// ---------------------------------------------------------------------------
// Kernel D: rank-by-count DESCENDING argsort of y; scatter s=100*y + indices.
// ---------------------------------------------------------------------------
__global__ void __launch_bounds__(256)
rank_scatter_y() {
    const unsigned FULL = 0xffffffffu;
    __shared__ float sy[NN];
    float4* sy4 = (float4*)sy;
    const float4* y4 = (const float4*)g_y;
    for (int i = threadIdx.x; i < NN / 4; i += 256) sy4[i] = y4[i];
    __syncthreads();

    int gw   = blockIdx.x * 8 + (threadIdx.x >> 5);
    int lane = threadIdx.x & 31;
    int row  = gw * 2 + (lane >> 4);
    int q    = lane & 15;
    float yi = sy[row];
    int cnt = 0;
    #pragma unroll 8
    for (int t = 0; t < NN / 64; t++) {
        int j = t * 64 + q * 4;
        float4 v = sy4[j >> 2];
        cnt += (v.x > yi) || (v.x == yi && (j + 0) < row);
        cnt += (v.y > yi) || (v.y == yi && (j + 1) < row);
        cnt += (v.z > yi) || (v.z == yi && (j + 2) < row);
        cnt += (v.w > yi) || (v.w == yi && (j + 3) < row);
    }
    cnt += __shfl_xor_sync(FULL, cnt, 1);
    cnt += __shfl_xor_sync(FULL, cnt, 2);
    cnt += __shfl_xor_sync(FULL, cnt, 4);
    cnt += __shfl_xor_sync(FULL, cnt, 8);
    if (q == 0) {
        g_ss[cnt]   = yi * 100.0f;
        g_sidx[cnt] = row;
    }
}

// ---------------------------------------------------------------------------
// Kernel C: soft_rank via non-increasing isotonic regression (PAV), then
// diff_sum and final loss. Single block, 1024 threads.
//  - float4/int4 global loads
//  - pre-blocks packed as float4 {sum, cnt, start, 0} -> 1 LDS.128 per PAV step
//  - serial PAV software-pipelined (prefetch next pre-block)
// ---------------------------------------------------------------------------
__global__ void __launch_bounds__(1024)
rank_kernel(float* out, int out_size) {
    extern __shared__ char smem_raw[];
    float4* pb     = (float4*)smem_raw;            // NN  (pre-blocks / stack)
    float*  s      = (float*)(pb + NN);            // NN  (descending)
    float*  r      = s + NN;                       // NN  (zc prefix, then ranks)
    float*  fmean  = r + NN;                       // NN
    int*    idx    = (int*)(fmean + NN);           // NN
    int*    bstart = idx + NN;                     // NN+1
    int*    fstart = bstart + NN + 1;              // NN+1

    __shared__ int   warpTotI[32];
    __shared__ float warpTotF[32];
    __shared__ int   warpOffI[32];
    __shared__ float warpOffF[32];
    __shared__ int   s_m, s_nb;
    __shared__ float s_red[32];

    const unsigned FULL = 0xffffffffu;
    int tid  = threadIdx.x;
    int lane = tid & 31;
    int warp = tid >> 5;
    const int base = tid * 4;

    float4 sv = ((const float4*)g_ss)[tid];
    int4   si = ((const int4*)g_sidx)[tid];
    ((float4*)s)[tid] = sv;
    ((int4*)idx)[tid] = si;
    __syncthreads();

    // boundary flags + z sums (registers)
    float prev = (tid == 0) ? sv.x : s[base - 1];
    int b0 = (base > 0) ? (prev - sv.x > 1.0f) : 0;
    int b1 = (sv.x - sv.y > 1.0f);
    int b2 = (sv.y - sv.z > 1.0f);
    int b3 = (sv.z - sv.w > 1.0f);
    int cb = b0 + b1 + b2 + b3;
    float zt = (sv.x + sv.y + sv.z + sv.w) - (float)(4 * NN - 4 * base - 6);

    // joint warp scans
    int ic = cb; float fc = zt;
    for (int off = 1; off < 32; off <<= 1) {
        int   ui = __shfl_up_sync(FULL, ic, off);
        float uf = __shfl_up_sync(FULL, fc, off);
        if (lane >= off) { ic += ui; fc += uf; }
    }
    if (lane == 31) { warpTotI[warp] = ic; warpTotF[warp] = fc; }
    __syncthreads();
    if (warp == 0) {
        int   ti = warpTotI[lane];
        float tf = warpTotF[lane];
        int   vi = ti; float vf = tf;
        for (int off = 1; off < 32; off <<= 1) {
            int   ui = __shfl_up_sync(FULL, vi, off);
            float uf = __shfl_up_sync(FULL, vf, off);
            if (lane >= off) { vi += ui; vf += uf; }
        }
        warpOffI[lane] = vi - ti;
        warpOffF[lane] = vf - tf;
    }
    __syncthreads();
    int   exI = warpOffI[warp] + (ic - cb);
    float exF = warpOffF[warp] + (fc - zt);

    // write bstart flags and zc prefix
    {
        int cc = exI;
        float zc = exF;
        cc += b0; if (b0) bstart[cc] = base + 0;
        zc += sv.x - (float)(NN - base - 0); r[base + 0] = zc;
        cc += b1; if (b1) bstart[cc] = base + 1;
        zc += sv.y - (float)(NN - base - 1); r[base + 1] = zc;
        cc += b2; if (b2) bstart[cc] = base + 2;
        zc += sv.z - (float)(NN - base - 2); r[base + 2] = zc;
        cc += b3; if (b3) bstart[cc] = base + 3;
        zc += sv.w - (float)(NN - base - 3); r[base + 3] = zc;
        if (tid == 0) bstart[0] = 0;
        if (tid == 1023) { s_m = cc + 1; bstart[cc + 1] = NN; }
    }
    __syncthreads();

    // pre-block packed structs
    int m = s_m;
    for (int b = tid; b < m; b += 1024) {
        int st_ = bstart[b], en = bstart[b + 1];
        float lo_ = (st_ > 0) ? r[st_ - 1] : 0.f;
        pb[b] = make_float4(r[en - 1] - lo_, (float)(en - st_), (float)st_, 0.f);
    }
    __syncthreads();

    // serial PAV over m pre-blocks (thread 0), prefetched
    if (tid == 0) {
        int sp = 0;
        float4 c0 = pb[0];
        float tsum = c0.x, tcnt = c0.y, tstf = c0.z;
        float4 nxt = (m > 1) ? pb[1] : make_float4(0, 0, 0, 0);
        for (int b = 1; b < m; b++) {
            float4 c = nxt;
            if (b + 1 < m) nxt = pb[b + 1];
            float nsum = c.x, ncnt = c.y, nstf = c.z;
            bool havetop = true;
            while (havetop && tsum * ncnt <= nsum * tcnt) {
                nsum += tsum; ncnt += tcnt; nstf = tstf;
                if (sp > 0) {
                    sp--;
                    float4 tpv = pb[sp];
                    tsum = tpv.x; tcnt = tpv.y; tstf = tpv.z;
                } else {
                    havetop = false;
                }
            }
            if (havetop) {
                pb[sp] = make_float4(tsum, tcnt, tstf, 0.f);
                sp++;
            }
            tsum = nsum; tcnt = ncnt; tstf = nstf;
        }
        for (int q_ = 0; q_ < sp; q_++) {
            float4 v = pb[q_];
            fstart[q_] = (int)v.z;
            fmean[q_]  = v.x / v.y;
        }
        fstart[sp] = (int)tstf;
        fmean[sp]  = tsum / tcnt;
        fstart[sp + 1] = NN;
        s_nb = sp + 1;
    }
    __syncthreads();

    // expand + scatter r[idx[k]] = s[k] - v(block(k))
    int nb = s_nb;
    #pragma unroll
    for (int e = 0; e < 4; e++) {
        int k = base + e;
        int l = 0, h = nb;
        while (l + 1 < h) {
            int mid = (l + h) >> 1;
            if (fstart[mid] <= k) l = mid; else h = mid;
        }
        float sval = (e == 0) ? sv.x : (e == 1) ? sv.y : (e == 2) ? sv.z : sv.w;
        int dst = (e == 0) ? si.x : (e == 1) ? si.y : (e == 2) ? si.z : si.w;
        r[dst] = sval - fmean[l];
    }
    __syncthreads();

    float acc = 0.f;
    for (int i = tid; i < NN - 1; i += 1024) acc += fabsf(r[i + 1] - r[i]);
    for (int off = 16; off; off >>= 1) acc += __shfl_down_sync(FULL, acc, off);
    if (lane == 0) s_red[warp] = acc;
    __syncthreads();
    if (warp == 0) {
        float a2 = s_red[lane];
        for (int off = 16; off; off >>= 1) a2 += __shfl_down_sync(FULL, a2, off);
        if (lane == 0) {
            float xi = 1.0f - 3.0f * a2 / ((float)NN * (float)NN - 1.0f);
            out[0] = -xi;
            if (out_size > 1) out[1] = xi;
        }
    }
}

// ---------------------------------------------------------------------------
extern "C" void kernel_launch(void* const* d_in, const int* in_sizes, int n_in,
                              void* d_out, int out_size) {
    const float* preds  = (const float*)d_in[0];
    const float* target = (const float*)d_in[1];
    float* out = (float*)d_out;

    size_t smem = (size_t)NN * 40 + 8;   // pb(16)+s+r+fmean(12)+idx+bstart+fstart(12)
    static int configured = 0;
    if (!configured) {
        cudaFuncSetAttribute(rank_kernel,
                             cudaFuncAttributeMaxDynamicSharedMemorySize,
                             (int)smem);
        configured = 1;
    }

    rank_scatter_pairs<<<256, 256>>>(preds, target);
    ysoft_kernel<<<NN / 8, 256>>>();
    rank_scatter_y<<<256, 256>>>();
    rank_kernel<<<1, 1024, smem>>>(out, out_size);
}